// round 2
// baseline (speedup 1.0000x reference)
#include <cuda_runtime.h>
#include <cstdint>

#define Tn 512
#define Bn 128
#define Hn 256
#define Gn 1024
#define NBLK 128

// Scratch (device globals: no cudaMalloc allowed)
__device__ float g_pre0[(size_t)Tn * Gn * Bn];   // [t][gatecol][b]  (256 MB)
__device__ float g_hbuf[2][2][Hn * Bn];          // [layer][pingpong][h][b]
__device__ float g_gates1[Gn * Bn];              // [gatecol][b] layer-1 partial
__device__ volatile unsigned g_bar_gen;
__device__ unsigned g_bar_cnt;

__device__ __forceinline__ float fsig(float x) {
    return __fdividef(1.0f, 1.0f + __expf(-x));
}
__device__ __forceinline__ float ftanh2(float x) {
    float e = __expf(2.0f * x);
    return 1.0f - __fdividef(2.0f, e + 1.0f);   // safe at +/-inf
}

__device__ __forceinline__ void grid_barrier() {
    __threadfence();       // release this thread's prior writes (all threads do this)
    __syncthreads();
    if (threadIdx.x == 0) {
        unsigned gen = g_bar_gen;
        if (atomicAdd(&g_bar_cnt, 1u) == (unsigned)(NBLK - 1)) {
            g_bar_cnt = 0u;
            __threadfence();
            g_bar_gen = gen + 1u;
        } else {
            while (g_bar_gen == gen) { __nanosleep(32); }
            __threadfence();
        }
    }
    __syncthreads();
}

// ---------------------------------------------------------------------------
// Precompute: g_pre0[t][g][b] = b_ih0[g] + b_hh0[g] + sum_k x[t][b][k]*W_ih0[g][k]
// Tile: 64 g x 64 b per block, K-chunks of 32. grid = (16 gt, 2 bt, 512 t)
// ---------------------------------------------------------------------------
__global__ __launch_bounds__(256, 1) void precompute_kernel(
    const float* __restrict__ x, const float* __restrict__ W_ih,
    const float* __restrict__ b_ih, const float* __restrict__ b_hh)
{
    __shared__ __align__(16) float Xs[32][68];   // [k][b]
    __shared__ __align__(16) float Ws[32][68];   // [k][g]
    const int gt = blockIdx.x;
    const int bt = blockIdx.y;
    const int t  = blockIdx.z;
    const int tid = threadIdx.x;
    const int tyg = tid >> 4;    // g group 0..15
    const int txg = tid & 15;    // b group 0..15

    const float* xbase = x + (size_t)t * (Bn * Hn) + (size_t)(bt * 64) * Hn;
    const float* wbase = W_ih + (size_t)(gt * 64) * Hn;   // layer 0 at offset 0

    float acc[4][4];
#pragma unroll
    for (int i = 0; i < 4; i++)
#pragma unroll
        for (int j = 0; j < 4; j++) acc[i][j] = 0.f;

    for (int kc = 0; kc < Hn; kc += 32) {
#pragma unroll
        for (int i = 0; i < 2; i++) {
            int f = tid + i * 256;          // 0..511
            int r = f >> 3;                 // 0..63 row within tile
            int k4 = (f & 7) * 4;           // 0..28
            float4 xv = *reinterpret_cast<const float4*>(xbase + (size_t)r * Hn + kc + k4);
            float4 wv = *reinterpret_cast<const float4*>(wbase + (size_t)r * Hn + kc + k4);
            Xs[k4 + 0][r] = xv.x; Xs[k4 + 1][r] = xv.y; Xs[k4 + 2][r] = xv.z; Xs[k4 + 3][r] = xv.w;
            Ws[k4 + 0][r] = wv.x; Ws[k4 + 1][r] = wv.y; Ws[k4 + 2][r] = wv.z; Ws[k4 + 3][r] = wv.w;
        }
        __syncthreads();
#pragma unroll
        for (int kk = 0; kk < 32; kk++) {
            float4 xv = *reinterpret_cast<const float4*>(&Xs[kk][txg * 4]);
            float4 wv = *reinterpret_cast<const float4*>(&Ws[kk][tyg * 4]);
            acc[0][0] += wv.x * xv.x; acc[0][1] += wv.x * xv.y; acc[0][2] += wv.x * xv.z; acc[0][3] += wv.x * xv.w;
            acc[1][0] += wv.y * xv.x; acc[1][1] += wv.y * xv.y; acc[1][2] += wv.y * xv.z; acc[1][3] += wv.y * xv.w;
            acc[2][0] += wv.z * xv.x; acc[2][1] += wv.z * xv.y; acc[2][2] += wv.z * xv.z; acc[2][3] += wv.z * xv.w;
            acc[3][0] += wv.w * xv.x; acc[3][1] += wv.w * xv.y; acc[3][2] += wv.w * xv.z; acc[3][3] += wv.w * xv.w;
        }
        __syncthreads();
    }
    float* outp = g_pre0 + (size_t)t * (Gn * Bn)
                + (size_t)(gt * 64 + tyg * 4) * Bn + bt * 64 + txg * 4;
#pragma unroll
    for (int i = 0; i < 4; i++) {
        int g = gt * 64 + tyg * 4 + i;
        float bias = __ldg(b_ih + g) + __ldg(b_hh + g);
        float4 v = make_float4(acc[i][0] + bias, acc[i][1] + bias,
                               acc[i][2] + bias, acc[i][3] + bias);
        *reinterpret_cast<float4*>(outp + (size_t)i * Bn) = v;
    }
}

// ---------------------------------------------------------------------------
// Persistent recurrence. 128 blocks x 256 threads, all co-resident.
// Blocks 0..63  : layer-0 gates (recurrent GEMM + pre0 + elementwise) for 4 h-cols
// Blocks 64..127: layer-1 recurrent partial (h1 @ W_hh1 + bias) for 4 h-cols
//   -- barrier --
// All blocks    : layer-1 input proj (h0_new @ W_ih1) + elementwise for 2 h-cols
//   -- barrier --
// Column grouping: local col c = hi*4 + gate  ->  global gate col = gate*256 + hbase + hi
// ---------------------------------------------------------------------------
__global__ __launch_bounds__(256, 1) void lstm_persistent(
    const float* __restrict__ W_ih, const float* __restrict__ W_hh,
    const float* __restrict__ b_ih, const float* __restrict__ b_hh,
    float* __restrict__ out)
{
    __shared__ __align__(16) float Wsm[256][16];  // phase-1 W_hh slice [k][c]
    __shared__ __align__(16) float Wsm2[256][8];  // phase-2 W_ih1 slice [k][c2]
    __shared__ float biass[16];
    __shared__ __align__(16) float BufS[32 * 132]; // Hs[32][132] / Csm[16][132] overlay

    const int tid = threadIdx.x;
    const int blk = blockIdx.x;
    const bool isL0 = blk < 64;
    const int hbase  = (isL0 ? blk : blk - 64) * 4;  // phase-1: 4 h-cols
    const int hbase2 = blk * 2;                      // phase-2: 2 h-cols
    const int ryg = tid >> 3;   // 0..31 -> rows ryg*4..+3 (batch)
    const int cxg = tid & 7;    // 0..7  -> phase1 cols cxg*2..+1, phase2 col cxg

    // Load phase-1 weights (W_hh of my layer), transposed to [k][c]
    {
        const float* Wl = W_hh + (isL0 ? 0 : (size_t)Gn * Hn);
        int c  = tid >> 4;            // 0..15
        int kb = (tid & 15) * 16;     // 16 k per thread
        int gc = (c & 3) * Hn + hbase + (c >> 2);
        const float* wr = Wl + (size_t)gc * Hn + kb;
#pragma unroll
        for (int k = 0; k < 16; k++) Wsm[kb + k][c] = __ldg(wr + k);
    }
    if (!isL0 && tid < 16) {
        int c = tid;
        int gc = (c & 3) * Hn + hbase + (c >> 2);
        biass[c] = __ldg(b_ih + Gn + gc) + __ldg(b_hh + Gn + gc);
    }
    // Load phase-2 weights (W_ih layer 1), transposed to [k][c2]
    {
        int c2 = tid >> 5;            // 0..7
        int kb = (tid & 31) * 8;      // 8 k per thread
        int gc2 = (c2 & 3) * Hn + hbase2 + (c2 >> 2);
        const float* wr = W_ih + (size_t)Gn * Hn + (size_t)gc2 * Hn + kb;
#pragma unroll
        for (int k = 0; k < 8; k++) Wsm2[kb + k][c2] = __ldg(wr + k);
    }
    // Zero initial h state (pingpong slot 0) for both layers
    {
        int idx = blk * 256 + tid;    // exactly covers 32768
        g_hbuf[0][0][idx] = 0.f;
        g_hbuf[1][0][idx] = 0.f;
    }
    float c0reg0 = 0.f, c0reg1 = 0.f;  // layer-0 cell state (register-resident)
    float c1reg = 0.f;                  // layer-1 cell state

    const size_t OUT_H = (size_t)Tn * Bn * Hn;
    const size_t OUT_C = OUT_H + 2 * (size_t)Bn * Hn;

    grid_barrier();   // h zero-init visible

    for (int t = 0; t < Tn; t++) {
        const int pp = t & 1;
        // ================= phase 1 =================
        const float* hT = g_hbuf[isL0 ? 0 : 1][pp];
        float a00=0,a01=0,a10=0,a11=0,a20=0,a21=0,a30=0,a31=0;
        for (int kc = 0; kc < 8; kc++) {
#pragma unroll
            for (int i = 0; i < 4; i++) {
                int f = tid + i * 256;          // 0..1023
                int r = f >> 5;                 // 0..31 (k within chunk)
                int c4 = (f & 31) * 4;          // 0..124 (b)
                float4 v = __ldcg(reinterpret_cast<const float4*>(
                    hT + (size_t)(kc * 32 + r) * Bn + c4));
                *reinterpret_cast<float4*>(&BufS[r * 132 + c4]) = v;
            }
            __syncthreads();
#pragma unroll
            for (int kk = 0; kk < 32; kk++) {
                float4 a = *reinterpret_cast<const float4*>(&BufS[kk * 132 + ryg * 4]);
                float2 w = *reinterpret_cast<const float2*>(&Wsm[kc * 32 + kk][cxg * 2]);
                a00 += a.x * w.x; a01 += a.x * w.y;
                a10 += a.y * w.x; a11 += a.y * w.y;
                a20 += a.z * w.x; a21 += a.z * w.y;
                a30 += a.w * w.x; a31 += a.w * w.y;
            }
            __syncthreads();
        }
        // stage tile to smem as Csm[c][b] (width 132 kills bank conflicts)
        {
            int cb0 = (cxg * 2)     * 132 + ryg * 4;
            int cb1 = (cxg * 2 + 1) * 132 + ryg * 4;
            BufS[cb0+0]=a00; BufS[cb0+1]=a10; BufS[cb0+2]=a20; BufS[cb0+3]=a30;
            BufS[cb1+0]=a01; BufS[cb1+1]=a11; BufS[cb1+2]=a21; BufS[cb1+3]=a31;
        }
        __syncthreads();
        if (isL0) {
            const float* pre = g_pre0 + (size_t)t * (Gn * Bn);
#pragma unroll
            for (int j2 = 0; j2 < 2; j2++) {
                int e = tid + j2 * 256;
                int b = e & 127;
                int hi = e >> 7;                 // 0..3
                int hcol = hbase + hi;
                float gi = BufS[(hi*4+0)*132 + b] + __ldg(pre + (size_t)(0*Hn + hcol) * Bn + b);
                float gf = BufS[(hi*4+1)*132 + b] + __ldg(pre + (size_t)(1*Hn + hcol) * Bn + b);
                float gg = BufS[(hi*4+2)*132 + b] + __ldg(pre + (size_t)(2*Hn + hcol) * Bn + b);
                float go = BufS[(hi*4+3)*132 + b] + __ldg(pre + (size_t)(3*Hn + hcol) * Bn + b);
                float cprev = j2 ? c0reg1 : c0reg0;
                float cn = fsig(gf) * cprev + fsig(gi) * ftanh2(gg);
                if (j2) c0reg1 = cn; else c0reg0 = cn;
                float hn = fsig(go) * ftanh2(cn);
                g_hbuf[0][pp ^ 1][hcol * Bn + b] = hn;
                if (t == Tn - 1) {
                    out[OUT_H + (size_t)b * Hn + hcol] = hn;   // h_n layer 0
                    out[OUT_C + (size_t)b * Hn + hcol] = cn;   // c_n layer 0
                }
            }
        } else {
#pragma unroll
            for (int j2 = 0; j2 < 8; j2++) {
                int e = tid + j2 * 256;          // 0..2047
                int b = e & 127;
                int c = e >> 7;                  // 0..15
                int gc = (c & 3) * Hn + hbase + (c >> 2);
                g_gates1[gc * Bn + b] = BufS[c * 132 + b] + biass[c];
            }
        }
        grid_barrier();

        // ================= phase 2 =================
        const float* h0n = g_hbuf[0][pp ^ 1];
        float p0=0,p1=0,p2=0,p3=0;
        for (int kc = 0; kc < 8; kc++) {
#pragma unroll
            for (int i = 0; i < 4; i++) {
                int f = tid + i * 256;
                int r = f >> 5;
                int c4 = (f & 31) * 4;
                float4 v = __ldcg(reinterpret_cast<const float4*>(
                    h0n + (size_t)(kc * 32 + r) * Bn + c4));
                *reinterpret_cast<float4*>(&BufS[r * 132 + c4]) = v;
            }
            __syncthreads();
#pragma unroll
            for (int kk = 0; kk < 32; kk++) {
                float4 a = *reinterpret_cast<const float4*>(&BufS[kk * 132 + ryg * 4]);
                float w = Wsm2[kc * 32 + kk][cxg];
                p0 += a.x * w; p1 += a.y * w; p2 += a.z * w; p3 += a.w * w;
            }
            __syncthreads();
        }
        {
            int gc2 = (cxg & 3) * Hn + hbase2 + (cxg >> 2);
            const float* gp = g_gates1 + (size_t)gc2 * Bn + ryg * 4;
            int cb = cxg * 132 + ryg * 4;
            BufS[cb+0] = p0 + __ldcg(gp + 0);
            BufS[cb+1] = p1 + __ldcg(gp + 1);
            BufS[cb+2] = p2 + __ldcg(gp + 2);
            BufS[cb+3] = p3 + __ldcg(gp + 3);
        }
        __syncthreads();
        {
            int b  = tid & 127;
            int hi = tid >> 7;                  // 0..1
            int hcol = hbase2 + hi;
            float gi = BufS[(hi*4+0)*132 + b];
            float gf = BufS[(hi*4+1)*132 + b];
            float gg = BufS[(hi*4+2)*132 + b];
            float go = BufS[(hi*4+3)*132 + b];
            float cn = fsig(gf) * c1reg + fsig(gi) * ftanh2(gg);
            c1reg = cn;
            float hn = fsig(go) * ftanh2(cn);
            g_hbuf[1][pp ^ 1][hcol * Bn + b] = hn;
            out[(size_t)t * (Bn * Hn) + (size_t)b * Hn + hcol] = hn;
            if (t == Tn - 1) {
                out[OUT_H + (size_t)Bn * Hn + (size_t)b * Hn + hcol] = hn;  // h_n layer 1
                out[OUT_C + (size_t)Bn * Hn + (size_t)b * Hn + hcol] = cn;  // c_n layer 1
            }
        }
        grid_barrier();
    }
}

extern "C" void kernel_launch(void* const* d_in, const int* in_sizes, int n_in,
                              void* d_out, int out_size) {
    (void)in_sizes; (void)n_in; (void)out_size;
    const float* x    = (const float*)d_in[0];
    const float* W_ih = (const float*)d_in[1];
    const float* W_hh = (const float*)d_in[2];
    const float* b_ih = (const float*)d_in[3];
    const float* b_hh = (const float*)d_in[4];
    float* out = (float*)d_out;

    dim3 gPre(16, 2, 512);
    precompute_kernel<<<gPre, 256>>>(x, W_ih, b_ih, b_hh);
    lstm_persistent<<<NBLK, 256>>>(W_ih, W_hh, b_ih, b_hh, out);
}

// round 3
// speedup vs baseline: 1.1647x; 1.1647x over previous
#include <cuda_runtime.h>
#include <cstdint>

#define Tn 512
#define Bn 128
#define Hn 256
#define Gn 1024
#define NBLK 128
#define CHUNK 64

// ---------------- device scratch (no cudaMalloc allowed) ----------------
__device__ float g_pre0[(size_t)Tn * Gn * Bn];   // [t][gatecol][b]
__device__ float g_h0[2][Hn * Bn];               // layer0 h, ping-pong [h][b]
__device__ float g_h1[2][Hn * Bn];               // layer1 h, ping-pong [h][b]
__device__ volatile unsigned g_bar_gen = 0;
__device__ unsigned g_bar_cnt = 0;

__device__ __forceinline__ float fsig(float x) {
    return __fdividef(1.0f, 1.0f + __expf(-x));
}
__device__ __forceinline__ float ftanh2(float x) {
    float e = __expf(2.0f * x);
    return 1.0f - __fdividef(2.0f, e + 1.0f);
}

__device__ __forceinline__ void grid_barrier() {
    __syncthreads();
    if (threadIdx.x == 0) {
        unsigned gen = g_bar_gen;
        __threadfence();
        if (atomicAdd(&g_bar_cnt, 1u) == (unsigned)(NBLK - 1)) {
            g_bar_cnt = 0u;
            __threadfence();
            g_bar_gen = gen + 1u;
        } else {
            while (g_bar_gen == gen) {}
            __threadfence();
        }
    }
    __syncthreads();
}

// packed f32x2 helpers
__device__ __forceinline__ void ffma2(unsigned long long& d,
                                      unsigned long long a,
                                      unsigned long long b) {
    asm volatile("fma.rn.f32x2 %0, %1, %2, %0;" : "+l"(d) : "l"(a), "l"(b));
}
__device__ __forceinline__ unsigned long long dup2(float w) {
    unsigned long long r;
    asm("mov.b64 %0, {%1, %1};" : "=l"(r) : "f"(w));
    return r;
}
__device__ __forceinline__ void cp16(float* dst, const float* src) {
    unsigned d = (unsigned)__cvta_generic_to_shared(dst);
    asm volatile("cp.async.cg.shared.global [%0], [%1], 16;" :: "r"(d), "l"(src));
}

// ---------------------------------------------------------------------------
// Precompute: g_pre0[t][g][b] = b_ih0[g]+b_hh0[g] + sum_k x[t][b][k]*W_ih0[g][k]
// ---------------------------------------------------------------------------
__global__ __launch_bounds__(256) void precompute_kernel(
    const float* __restrict__ x, const float* __restrict__ W_ih,
    const float* __restrict__ b_ih, const float* __restrict__ b_hh)
{
    __shared__ __align__(16) float Xs[32][68];
    __shared__ __align__(16) float Ws[32][68];
    const int gt = blockIdx.x;
    const int bt = blockIdx.y;
    const int t  = blockIdx.z;
    const int tid = threadIdx.x;
    const int tyg = tid >> 4;
    const int txg = tid & 15;

    const float* xbase = x + (size_t)t * (Bn * Hn) + (size_t)(bt * 64) * Hn;
    const float* wbase = W_ih + (size_t)(gt * 64) * Hn;

    float acc[4][4];
#pragma unroll
    for (int i = 0; i < 4; i++)
#pragma unroll
        for (int j = 0; j < 4; j++) acc[i][j] = 0.f;

    for (int kc = 0; kc < Hn; kc += 32) {
#pragma unroll
        for (int i = 0; i < 2; i++) {
            int f = tid + i * 256;
            int r = f >> 3;
            int k4 = (f & 7) * 4;
            float4 xv = *reinterpret_cast<const float4*>(xbase + (size_t)r * Hn + kc + k4);
            float4 wv = *reinterpret_cast<const float4*>(wbase + (size_t)r * Hn + kc + k4);
            Xs[k4 + 0][r] = xv.x; Xs[k4 + 1][r] = xv.y; Xs[k4 + 2][r] = xv.z; Xs[k4 + 3][r] = xv.w;
            Ws[k4 + 0][r] = wv.x; Ws[k4 + 1][r] = wv.y; Ws[k4 + 2][r] = wv.z; Ws[k4 + 3][r] = wv.w;
        }
        __syncthreads();
#pragma unroll
        for (int kk = 0; kk < 32; kk++) {
            float4 xv = *reinterpret_cast<const float4*>(&Xs[kk][txg * 4]);
            float4 wv = *reinterpret_cast<const float4*>(&Ws[kk][tyg * 4]);
            acc[0][0] += wv.x * xv.x; acc[0][1] += wv.x * xv.y; acc[0][2] += wv.x * xv.z; acc[0][3] += wv.x * xv.w;
            acc[1][0] += wv.y * xv.x; acc[1][1] += wv.y * xv.y; acc[1][2] += wv.y * xv.z; acc[1][3] += wv.y * xv.w;
            acc[2][0] += wv.z * xv.x; acc[2][1] += wv.z * xv.y; acc[2][2] += wv.z * xv.z; acc[2][3] += wv.z * xv.w;
            acc[3][0] += wv.w * xv.x; acc[3][1] += wv.w * xv.y; acc[3][2] += wv.w * xv.z; acc[3][3] += wv.w * xv.w;
        }
        __syncthreads();
    }
    float* outp = g_pre0 + (size_t)t * (Gn * Bn)
                + (size_t)(gt * 64 + tyg * 4) * Bn + bt * 64 + txg * 4;
#pragma unroll
    for (int i = 0; i < 4; i++) {
        int g = gt * 64 + tyg * 4 + i;
        float bias = __ldg(b_ih + g) + __ldg(b_hh + g);
        float4 v = make_float4(acc[i][0] + bias, acc[i][1] + bias,
                               acc[i][2] + bias, acc[i][3] + bias);
        *reinterpret_cast<float4*>(outp + (size_t)i * Bn) = v;
    }
}

// ---------------------------------------------------------------------------
// Persistent skewed recurrence. 128 blocks x 256 threads (1 CTA/SM).
// Iteration i (0..Tn): layer0 computes step i (if i<Tn), layer1 computes step
// i-1 (if i>=1). Both read only state written at iteration i-1 -> ONE barrier.
// Block owns h-cols {2*blk, 2*blk+1} of BOTH layers (16 gate-cols total).
// Thread (ks,bs,cs): ks=k-slot(4), bs=8 batch-pairs, cs=1 L0 gcol + 1 L1 gcol.
// ---------------------------------------------------------------------------
// smem layout (dynamic):
//   WsA  : ulonglong2[256*8]  (wL0dup, wL1a_dup)           32768 B @ 0
//   WsB  : u64[256*8]         (wL1b_dup)                   16384 B @ 32768
//   Hs0  : float[64*128]                                   32768 B @ 49152
//   Hs1  : float[64*128]                                   32768 B @ 81920
//   part : float[16][4][132]                               33792 B @ 114688
#define SMEM_TOTAL 148480

__global__ __launch_bounds__(256, 1) void lstm_persistent(
    const float* __restrict__ W_ih, const float* __restrict__ W_hh,
    const float* __restrict__ b_ih, const float* __restrict__ b_hh,
    float* __restrict__ out)
{
    extern __shared__ __align__(16) char smraw[];
    ulonglong2* WsA = reinterpret_cast<ulonglong2*>(smraw);
    unsigned long long* WsB = reinterpret_cast<unsigned long long*>(smraw + 32768);
    float* Hs[2] = { reinterpret_cast<float*>(smraw + 49152),
                     reinterpret_cast<float*>(smraw + 81920) };
    float* part = reinterpret_cast<float*>(smraw + 114688);

    const int tid = threadIdx.x;
    const int blk = blockIdx.x;
    const int ks = tid >> 6;          // 0..3
    const int bs = (tid >> 3) & 7;    // 0..7  -> batch [bs*16, bs*16+16)
    const int cs = tid & 7;           // 0..7  -> gate col pair

    // ---- setup: weights into smem (once) ----
    {
        const int g = (cs & 3) * Hn + 2 * blk + (cs >> 2);
        const float* wh0 = W_hh + (size_t)g * Hn;
        const float* wi1 = W_ih + (size_t)Gn * Hn + (size_t)g * Hn;
        const float* wh1 = W_hh + (size_t)Gn * Hn + (size_t)g * Hn;
        const int kg = tid >> 3;      // 0..31
#pragma unroll
        for (int j = 0; j < 8; j++) {
            int k = kg * 8 + j;
            WsA[k * 8 + cs] = make_ulonglong2(dup2(__ldg(wh0 + k)), dup2(__ldg(wi1 + k)));
            WsB[k * 8 + cs] = dup2(__ldg(wh1 + k));
        }
    }
    // elementwise identity: thread owns (hc, b)
    const int hc = tid >> 7;          // 0..1
    const int eb = tid & 127;         // batch
    const int hcol = 2 * blk + hc;
    float b1s[4];
#pragma unroll
    for (int g = 0; g < 4; g++)
        b1s[g] = __ldg(b_ih + Gn + g * Hn + hcol) + __ldg(b_hh + Gn + g * Hn + hcol);

    // zero both ping-pong slots of both layers
    {
        int idx = blk * 256 + tid;
        g_h0[0][idx] = 0.f; g_h0[1][idx] = 0.f;
        g_h1[0][idx] = 0.f; g_h1[1][idx] = 0.f;
    }
    float c0reg = 0.f, c1reg = 0.f;

    const size_t OUT_H = (size_t)Tn * Bn * Hn;
    const size_t OUT_C = OUT_H + 2 * (size_t)Bn * Hn;

    grid_barrier();

    for (int i = 0; i <= Tn; i++) {
        const int rslot = (i & 1) ^ 1;
        const int wslot = i & 1;
        const float* hA = g_h0[rslot];   // read by L0-recurrent AND L1-input
        const float* hB = g_h1[rslot];   // read by L1-recurrent

        // prefetch pre0 gate values for this thread's elementwise item (DRAM lat hidden)
        float pg[4] = {0.f, 0.f, 0.f, 0.f};
        if (i < Tn) {
            const float* pb = g_pre0 + (size_t)i * (Gn * Bn) + (size_t)hcol * Bn + eb;
#pragma unroll
            for (int g = 0; g < 4; g++) pg[g] = __ldg(pb + (size_t)g * Hn * Bn);
        }

        unsigned long long aL0[8], aL1[8];
#pragma unroll
        for (int p = 0; p < 8; p++) { aL0[p] = 0ull; aL1[p] = 0ull; }

        // ---- pipelined 8 chunks: 0..3 from hA (both GEMMs), 4..7 from hB (L1b) ----
        // issue chunk 0
        {
            const float* s = hA;
#pragma unroll
            for (int j = 0; j < 8; j++) {
                int f = tid + j * 256;
                int r = f >> 5, c4 = (f & 31) * 4;
                cp16(Hs[0] + r * 128 + c4, s + (size_t)r * Bn + c4);
            }
            asm volatile("cp.async.commit_group;");
        }
        for (int ch = 0; ch < 8; ch++) {
            asm volatile("cp.async.wait_group 0;");
            __syncthreads();
            if (ch < 8 - 1) {
                const int nc = ch + 1;
                const float* s = (nc < 4 ? hA : hB) + (size_t)(nc & 3) * CHUNK * Bn;
                float* dst = Hs[nc & 1];
#pragma unroll
                for (int j = 0; j < 8; j++) {
                    int f = tid + j * 256;
                    int r = f >> 5, c4 = (f & 31) * 4;
                    cp16(dst + r * 128 + c4, s + (size_t)r * Bn + c4);
                }
                asm volatile("cp.async.commit_group;");
            }
            const float* Hb = Hs[ch & 1];
            const int koff = (ch & 3) * CHUNK;
            if (ch < 4) {
                // L0 gemm + L1 input-proj on same h0 data
#pragma unroll
                for (int u = 0; u < 16; u++) {
                    const int kk = ks + u * 4;
                    const ulonglong2* hp = reinterpret_cast<const ulonglong2*>(Hb + kk * 128 + bs * 16);
                    ulonglong2 h0v = hp[0], h1v = hp[1], h2v = hp[2], h3v = hp[3];
                    ulonglong2 w = WsA[(koff + kk) * 8 + cs];
                    ffma2(aL0[0], h0v.x, w.x); ffma2(aL0[1], h0v.y, w.x);
                    ffma2(aL0[2], h1v.x, w.x); ffma2(aL0[3], h1v.y, w.x);
                    ffma2(aL0[4], h2v.x, w.x); ffma2(aL0[5], h2v.y, w.x);
                    ffma2(aL0[6], h3v.x, w.x); ffma2(aL0[7], h3v.y, w.x);
                    ffma2(aL1[0], h0v.x, w.y); ffma2(aL1[1], h0v.y, w.y);
                    ffma2(aL1[2], h1v.x, w.y); ffma2(aL1[3], h1v.y, w.y);
                    ffma2(aL1[4], h2v.x, w.y); ffma2(aL1[5], h2v.y, w.y);
                    ffma2(aL1[6], h3v.x, w.y); ffma2(aL1[7], h3v.y, w.y);
                }
            } else {
                // L1 recurrent gemm on h1 data
#pragma unroll
                for (int u = 0; u < 16; u++) {
                    const int kk = ks + u * 4;
                    const ulonglong2* hp = reinterpret_cast<const ulonglong2*>(Hb + kk * 128 + bs * 16);
                    ulonglong2 h0v = hp[0], h1v = hp[1], h2v = hp[2], h3v = hp[3];
                    unsigned long long w = WsB[(koff + kk) * 8 + cs];
                    ffma2(aL1[0], h0v.x, w); ffma2(aL1[1], h0v.y, w);
                    ffma2(aL1[2], h1v.x, w); ffma2(aL1[3], h1v.y, w);
                    ffma2(aL1[4], h2v.x, w); ffma2(aL1[5], h2v.y, w);
                    ffma2(aL1[6], h3v.x, w); ffma2(aL1[7], h3v.y, w);
                }
            }
        }

        // ---- k-slot partial store ----
        {
            float* p0 = part + (size_t)(cs * 4 + ks) * 132 + bs * 16;
            float* p1 = part + (size_t)((8 + cs) * 4 + ks) * 132 + bs * 16;
            ulonglong2* q0 = reinterpret_cast<ulonglong2*>(p0);
            ulonglong2* q1 = reinterpret_cast<ulonglong2*>(p1);
            q0[0] = make_ulonglong2(aL0[0], aL0[1]);
            q0[1] = make_ulonglong2(aL0[2], aL0[3]);
            q0[2] = make_ulonglong2(aL0[4], aL0[5]);
            q0[3] = make_ulonglong2(aL0[6], aL0[7]);
            q1[0] = make_ulonglong2(aL1[0], aL1[1]);
            q1[1] = make_ulonglong2(aL1[2], aL1[3]);
            q1[2] = make_ulonglong2(aL1[4], aL1[5]);
            q1[3] = make_ulonglong2(aL1[6], aL1[7]);
        }
        __syncthreads();

        // ---- elementwise layer 0 (step i) ----
        if (i < Tn) {
            float s[4];
#pragma unroll
            for (int g = 0; g < 4; g++) {
                const float* pr = part + (size_t)((hc * 4 + g) * 4) * 132 + eb;
                s[g] = pg[g] + pr[0] + pr[132] + pr[264] + pr[396];
            }
            float cn = fsig(s[1]) * c0reg + fsig(s[0]) * ftanh2(s[2]);
            c0reg = cn;
            float hn = fsig(s[3]) * ftanh2(cn);
            g_h0[wslot][hcol * Bn + eb] = hn;
            if (i == Tn - 1) {
                out[OUT_H + (size_t)eb * Hn + hcol] = hn;
                out[OUT_C + (size_t)eb * Hn + hcol] = cn;
            }
        }
        // ---- elementwise layer 1 (step i-1) ----
        if (i >= 1) {
            const int t1 = i - 1;
            float s[4];
#pragma unroll
            for (int g = 0; g < 4; g++) {
                const float* pr = part + (size_t)((8 + hc * 4 + g) * 4) * 132 + eb;
                s[g] = b1s[g] + pr[0] + pr[132] + pr[264] + pr[396];
            }
            float cn = fsig(s[1]) * c1reg + fsig(s[0]) * ftanh2(s[2]);
            c1reg = cn;
            float hn = fsig(s[3]) * ftanh2(cn);
            g_h1[wslot][hcol * Bn + eb] = hn;
            out[(size_t)t1 * (Bn * Hn) + (size_t)eb * Hn + hcol] = hn;
            if (i == Tn) {
                out[OUT_H + (size_t)Bn * Hn + (size_t)eb * Hn + hcol] = hn;
                out[OUT_C + (size_t)Bn * Hn + (size_t)eb * Hn + hcol] = cn;
            }
        }
        grid_barrier();
    }
}

extern "C" void kernel_launch(void* const* d_in, const int* in_sizes, int n_in,
                              void* d_out, int out_size) {
    (void)in_sizes; (void)n_in; (void)out_size;
    const float* x    = (const float*)d_in[0];
    const float* W_ih = (const float*)d_in[1];
    const float* W_hh = (const float*)d_in[2];
    const float* b_ih = (const float*)d_in[3];
    const float* b_hh = (const float*)d_in[4];
    float* out = (float*)d_out;

    cudaFuncSetAttribute(lstm_persistent,
                         cudaFuncAttributeMaxDynamicSharedMemorySize, SMEM_TOTAL);

    dim3 gPre(16, 2, 512);
    precompute_kernel<<<gPre, 256>>>(x, W_ih, b_ih, b_hh);
    lstm_persistent<<<NBLK, 256, SMEM_TOTAL>>>(W_ih, W_hh, b_ih, b_hh, out);
}

// round 4
// speedup vs baseline: 1.4828x; 1.2731x over previous
#include <cuda_runtime.h>
#include <cstdint>

#define Tn 512
#define Bn 128
#define Hn 256
#define Gn 1024
#define NBLK 128

// ---------------- device scratch ----------------
__device__ float g_pre0[(size_t)Tn * Gn * Bn];   // [t][gatecol][b]
__device__ float g_h0[2][Hn * Bn];               // [pp][h][b]
__device__ float g_h1[2][Hn * Bn];
__device__ volatile unsigned g_bar_gen = 0;
__device__ unsigned g_bar_cnt = 0;

__device__ __forceinline__ float fsig(float x) {
    return __fdividef(1.0f, 1.0f + __expf(-x));
}
__device__ __forceinline__ float ftanh2(float x) {
    float e = __expf(2.0f * x);
    return 1.0f - __fdividef(2.0f, e + 1.0f);
}
__device__ __forceinline__ void grid_barrier() {
    __syncthreads();
    if (threadIdx.x == 0) {
        unsigned gen = g_bar_gen;
        __threadfence();
        if (atomicAdd(&g_bar_cnt, 1u) == (unsigned)(NBLK - 1)) {
            g_bar_cnt = 0u;
            __threadfence();
            g_bar_gen = gen + 1u;
        } else {
            while (g_bar_gen == gen) {}
            __threadfence();
        }
    }
    __syncthreads();
}

__device__ __forceinline__ void ffma2(unsigned long long& d,
                                      unsigned long long a,
                                      unsigned long long b) {
    asm volatile("fma.rn.f32x2 %0, %1, %2, %0;" : "+l"(d) : "l"(a), "l"(b));
}
__device__ __forceinline__ unsigned long long dup2(float w) {
    unsigned long long r;
    asm("mov.b64 %0, {%1, %1};" : "=l"(r) : "f"(w));
    return r;
}
__device__ __forceinline__ unsigned long long pack2(float a, float b) {
    unsigned long long r;
    asm("mov.b64 %0, {%1, %2};" : "=l"(r) : "f"(a), "f"(b));
    return r;
}
__device__ __forceinline__ float2 unpack2(unsigned long long v) {
    float2 r;
    asm("mov.b64 {%0, %1}, %2;" : "=f"(r.x), "=f"(r.y) : "l"(v));
    return r;
}
__device__ __forceinline__ void cp16(float* dst, const float* src) {
    unsigned d = (unsigned)__cvta_generic_to_shared(dst);
    asm volatile("cp.async.cg.shared.global [%0], [%1], 16;" :: "r"(d), "l"(src));
}

// ---------------------------------------------------------------------------
// Precompute (FFMA2): g_pre0[t][g][b] = bias + sum_k x[t][b][k]*W_ih0[g][k]
// Block tile 64g x 64b, grid (16,2,512), 256 threads.
// ---------------------------------------------------------------------------
__global__ __launch_bounds__(256) void precompute_kernel(
    const float* __restrict__ x, const float* __restrict__ W_ih,
    const float* __restrict__ b_ih, const float* __restrict__ b_hh)
{
    __shared__ __align__(16) unsigned long long Xs[32][34];  // [k][bpair]
    __shared__ __align__(16) unsigned long long Ws[32][66];  // [k][g] dup'd
    const int gt = blockIdx.x;
    const int bt = blockIdx.y;
    const int t  = blockIdx.z;
    const int tid = threadIdx.x;
    const int txg = tid & 15;     // bpair group (2 pairs)
    const int tyg = tid >> 4;     // g group (4 g)

    const float* xb = x + ((size_t)t * Bn + bt * 64) * Hn;
    const float* wb = W_ih + (size_t)(gt * 64) * Hn;

    unsigned long long acc[4][2];
#pragma unroll
    for (int i = 0; i < 4; i++) { acc[i][0] = 0ull; acc[i][1] = 0ull; }

    for (int kc = 0; kc < Hn; kc += 32) {
        {   // Xs: pack batch pairs
            int bp = tid & 31;
            int k4 = (tid >> 5) * 4;
            const float* r0 = xb + (size_t)(2 * bp) * Hn + kc + k4;
            float4 a = *reinterpret_cast<const float4*>(r0);
            float4 b4 = *reinterpret_cast<const float4*>(r0 + Hn);
            Xs[k4 + 0][bp] = pack2(a.x, b4.x);
            Xs[k4 + 1][bp] = pack2(a.y, b4.y);
            Xs[k4 + 2][bp] = pack2(a.z, b4.z);
            Xs[k4 + 3][bp] = pack2(a.w, b4.w);
        }
#pragma unroll
        for (int j = 0; j < 2; j++) {  // Ws: dup'd weights
            int s = tid + j * 256;
            int g = s & 63;
            int k4 = (s >> 6) * 4;
            float4 w = *reinterpret_cast<const float4*>(wb + (size_t)g * Hn + kc + k4);
            Ws[k4 + 0][g] = dup2(w.x);
            Ws[k4 + 1][g] = dup2(w.y);
            Ws[k4 + 2][g] = dup2(w.z);
            Ws[k4 + 3][g] = dup2(w.w);
        }
        __syncthreads();
#pragma unroll
        for (int kk = 0; kk < 32; kk++) {
            ulonglong2 hv = *reinterpret_cast<const ulonglong2*>(&Xs[kk][txg * 2]);
            ulonglong2 wA = *reinterpret_cast<const ulonglong2*>(&Ws[kk][tyg * 4]);
            ulonglong2 wB = *reinterpret_cast<const ulonglong2*>(&Ws[kk][tyg * 4 + 2]);
            ffma2(acc[0][0], hv.x, wA.x); ffma2(acc[0][1], hv.y, wA.x);
            ffma2(acc[1][0], hv.x, wA.y); ffma2(acc[1][1], hv.y, wA.y);
            ffma2(acc[2][0], hv.x, wB.x); ffma2(acc[2][1], hv.y, wB.x);
            ffma2(acc[3][0], hv.x, wB.y); ffma2(acc[3][1], hv.y, wB.y);
        }
        __syncthreads();
    }
#pragma unroll
    for (int gi = 0; gi < 4; gi++) {
        int g = gt * 64 + tyg * 4 + gi;
        float bias = __ldg(b_ih + g) + __ldg(b_hh + g);
        float2 lo = unpack2(acc[gi][0]);
        float2 hi = unpack2(acc[gi][1]);
        float4 v = make_float4(lo.x + bias, lo.y + bias, hi.x + bias, hi.y + bias);
        *reinterpret_cast<float4*>(g_pre0 + (size_t)t * (Gn * Bn)
            + (size_t)g * Bn + bt * 64 + txg * 4) = v;
    }
}

// ---------------------------------------------------------------------------
// Persistent skewed recurrence. 128 CTAs x 512 threads.
// CTA(blk): bh = blk&1 (batch half, 64), cg = blk>>1 (h-cols [4cg,4cg+4)).
// Combined cols: 16 L0 gate-cols + 16 L1 gate-cols (cs = g*4+hcl).
// Iter i: L0 computes step i from h0[i-1]; L1 computes step i-1 from
// (h0[i-1], h1[i-2]). One grid barrier per iteration.
// smem: WsA ull2[256][16] 64K | WsB u64[256][16] 32K | H0 32K | H1 32K |
//       part f[32*4][72] 36K  -> 200704 B
// ---------------------------------------------------------------------------
#define SM_WB   65536
#define SM_H0   98304
#define SM_H1   131072
#define SM_PART 163840
#define SMEM_TOTAL 200704

__global__ __launch_bounds__(512, 1) void lstm_persistent(
    const float* __restrict__ W_ih, const float* __restrict__ W_hh,
    const float* __restrict__ b_ih, const float* __restrict__ b_hh,
    float* __restrict__ out)
{
    extern __shared__ __align__(16) char smraw[];
    ulonglong2* WsA = reinterpret_cast<ulonglong2*>(smraw);
    unsigned long long* WsB = reinterpret_cast<unsigned long long*>(smraw + SM_WB);
    float* Hbuf[2] = { reinterpret_cast<float*>(smraw + SM_H0),
                       reinterpret_cast<float*>(smraw + SM_H1) };
    float* part = reinterpret_cast<float*>(smraw + SM_PART);

    const int tid = threadIdx.x;
    const int blk = blockIdx.x;
    const int bh = blk & 1;
    const int cg = blk >> 1;
    // GEMM mapping
    const int ks = tid >> 7;          // 0..3 K slot
    const int bs = (tid >> 4) & 7;    // 0..7 -> 4 batch-pairs each
    const int cs = tid & 15;          // col pair (L0 col cs, L1 col cs)

    // ---- weights into smem (dup'd) ----
    {
        const int gc = (cs >> 2) * Hn + cg * 4 + (cs & 3);
        const float* wh0 = W_hh + (size_t)gc * Hn;
        const float* wi1 = W_ih + (size_t)Gn * Hn + (size_t)gc * Hn;
        const float* wh1 = W_hh + (size_t)Gn * Hn + (size_t)gc * Hn;
        const int kg = tid >> 4;      // 0..31
#pragma unroll
        for (int j = 0; j < 8; j++) {
            int k = kg * 8 + j;
            WsA[k * 16 + cs] = make_ulonglong2(dup2(__ldg(wh0 + k)), dup2(__ldg(wi1 + k)));
            WsB[k * 16 + cs] = dup2(__ldg(wh1 + k));
        }
    }
    // elementwise identity
    const int lay = tid >> 8;         // 0..1
    const int hcl = (tid >> 6) & 3;   // 0..3
    const int bl  = tid & 63;
    const int hcol = cg * 4 + hcl;
    const int b = bh * 64 + bl;
    float b1s[4];
#pragma unroll
    for (int g = 0; g < 4; g++)
        b1s[g] = __ldg(b_ih + Gn + g * Hn + hcol) + __ldg(b_hh + Gn + g * Hn + hcol);

    // zero init h buffers (both slots, both layers): 65536 floats each array
    {
        int idx = blk * 512 + tid;
        reinterpret_cast<float*>(g_h0)[idx] = 0.f;
        reinterpret_cast<float*>(g_h1)[idx] = 0.f;
    }
    float creg = 0.f;   // lay0 threads: c0 for (hcol,b); lay1 threads: c1

    const size_t OUT_H = (size_t)Tn * Bn * Hn;
    const size_t OUT_C = OUT_H + 2 * (size_t)Bn * Hn;

    grid_barrier();

    for (int i = 0; i <= Tn; i++) {
        const int rslot = (i & 1) ^ 1;
        const int wslot = i & 1;
        const float* hA = g_h0[rslot];
        const float* hB = g_h1[rslot];

        // prefetch pre0 gates (L0 elementwise operand)
        float pg[4] = {0.f, 0.f, 0.f, 0.f};
        if (lay == 0 && i < Tn) {
            const float* pb = g_pre0 + (size_t)i * (Gn * Bn);
#pragma unroll
            for (int g = 0; g < 4; g++)
                pg[g] = __ldg(pb + (size_t)(g * Hn + hcol) * Bn + b);
        }

        unsigned long long aL0[4], aL1[4];
#pragma unroll
        for (int p = 0; p < 4; p++) { aL0[p] = 0ull; aL1[p] = 0ull; }

        // ---- issue chunks 0,1 (hA rows 0-127, 128-255) ----
#pragma unroll
        for (int c0 = 0; c0 < 2; c0++) {
            const float* s = hA + (size_t)c0 * 128 * Bn;
#pragma unroll
            for (int j = 0; j < 4; j++) {
                int f = tid + j * 512;
                int r = f >> 4, c4 = (f & 15) * 4;
                cp16(Hbuf[c0] + r * 64 + c4, s + (size_t)r * Bn + bh * 64 + c4);
            }
            asm volatile("cp.async.commit_group;");
        }
#pragma unroll
        for (int ch = 0; ch < 4; ch++) {
            if (ch < 3) asm volatile("cp.async.wait_group 1;");
            else        asm volatile("cp.async.wait_group 0;");
            __syncthreads();
            const float* Hb = Hbuf[ch & 1];
            const int gkb = (ch & 1) * 128 + ks * 32;
            if (ch < 2) {
#pragma unroll
                for (int u = 0; u < 32; u++) {
                    const int kk = ks * 32 + u;
                    const int gk = gkb + u;
                    const ulonglong2* hp = reinterpret_cast<const ulonglong2*>(Hb + kk * 64 + bs * 8);
                    ulonglong2 h0v = hp[0], h1v = hp[1];
                    ulonglong2 w = WsA[gk * 16 + cs];
                    ffma2(aL0[0], h0v.x, w.x); ffma2(aL0[1], h0v.y, w.x);
                    ffma2(aL0[2], h1v.x, w.x); ffma2(aL0[3], h1v.y, w.x);
                    ffma2(aL1[0], h0v.x, w.y); ffma2(aL1[1], h0v.y, w.y);
                    ffma2(aL1[2], h1v.x, w.y); ffma2(aL1[3], h1v.y, w.y);
                }
            } else {
#pragma unroll
                for (int u = 0; u < 32; u++) {
                    const int kk = ks * 32 + u;
                    const int gk = gkb + u;
                    const ulonglong2* hp = reinterpret_cast<const ulonglong2*>(Hb + kk * 64 + bs * 8);
                    ulonglong2 h0v = hp[0], h1v = hp[1];
                    unsigned long long w = WsB[gk * 16 + cs];
                    ffma2(aL1[0], h0v.x, w); ffma2(aL1[1], h0v.y, w);
                    ffma2(aL1[2], h1v.x, w); ffma2(aL1[3], h1v.y, w);
                }
            }
            __syncthreads();   // buffer (ch&1) free for reuse
            if (ch < 2) {      // issue chunk ch+2 (hB rows)
                const float* s = hB + (size_t)(ch & 1) * 128 * Bn;
#pragma unroll
                for (int j = 0; j < 4; j++) {
                    int f = tid + j * 512;
                    int r = f >> 4, c4 = (f & 15) * 4;
                    cp16(Hbuf[ch & 1] + r * 64 + c4, s + (size_t)r * Bn + bh * 64 + c4);
                }
                asm volatile("cp.async.commit_group;");
            }
        }

        // ---- partial store: part[col*4+ks][72] ----
        {
            ulonglong2* q0 = reinterpret_cast<ulonglong2*>(part + (cs * 4 + ks) * 72 + bs * 8);
            q0[0] = make_ulonglong2(aL0[0], aL0[1]);
            q0[1] = make_ulonglong2(aL0[2], aL0[3]);
            ulonglong2* q1 = reinterpret_cast<ulonglong2*>(part + ((16 + cs) * 4 + ks) * 72 + bs * 8);
            q1[0] = make_ulonglong2(aL1[0], aL1[1]);
            q1[1] = make_ulonglong2(aL1[2], aL1[3]);
        }
        __syncthreads();

        // ---- elementwise: lay0 -> L0 step i, lay1 -> L1 step i-1 ----
        if (lay == 0) {
            if (i < Tn) {
                float s[4];
#pragma unroll
                for (int g = 0; g < 4; g++) {
                    const float* pr = part + (size_t)((g * 4 + hcl) * 4) * 72 + bl;
                    s[g] = pg[g] + pr[0] + pr[72] + pr[144] + pr[216];
                }
                float cn = fsig(s[1]) * creg + fsig(s[0]) * ftanh2(s[2]);
                creg = cn;
                float hn = fsig(s[3]) * ftanh2(cn);
                g_h0[wslot][hcol * Bn + b] = hn;
                if (i == Tn - 1) {
                    out[OUT_H + (size_t)b * Hn + hcol] = hn;
                    out[OUT_C + (size_t)b * Hn + hcol] = cn;
                }
            }
        } else {
            if (i >= 1) {
                const int t1 = i - 1;
                float s[4];
#pragma unroll
                for (int g = 0; g < 4; g++) {
                    const float* pr = part + (size_t)((16 + g * 4 + hcl) * 4) * 72 + bl;
                    s[g] = b1s[g] + pr[0] + pr[72] + pr[144] + pr[216];
                }
                float cn = fsig(s[1]) * creg + fsig(s[0]) * ftanh2(s[2]);
                creg = cn;
                float hn = fsig(s[3]) * ftanh2(cn);
                g_h1[wslot][hcol * Bn + b] = hn;
                out[(size_t)t1 * (Bn * Hn) + (size_t)b * Hn + hcol] = hn;
                if (i == Tn) {
                    out[OUT_H + (size_t)Bn * Hn + (size_t)b * Hn + hcol] = hn;
                    out[OUT_C + (size_t)Bn * Hn + (size_t)b * Hn + hcol] = cn;
                }
            }
        }
        grid_barrier();
    }
}

extern "C" void kernel_launch(void* const* d_in, const int* in_sizes, int n_in,
                              void* d_out, int out_size) {
    (void)in_sizes; (void)n_in; (void)out_size;
    const float* x    = (const float*)d_in[0];
    const float* W_ih = (const float*)d_in[1];
    const float* W_hh = (const float*)d_in[2];
    const float* b_ih = (const float*)d_in[3];
    const float* b_hh = (const float*)d_in[4];
    float* out = (float*)d_out;

    cudaFuncSetAttribute(lstm_persistent,
                         cudaFuncAttributeMaxDynamicSharedMemorySize, SMEM_TOTAL);

    dim3 gPre(16, 2, 512);
    precompute_kernel<<<gPre, 256>>>(x, W_ih, b_ih, b_hh);
    lstm_persistent<<<NBLK, 512, SMEM_TOTAL>>>(W_ih, W_hh, b_ih, b_hh, out);
}